// round 9
// baseline (speedup 1.0000x reference)
#include <cuda_runtime.h>
#include <cuda_bf16.h>
#include <cstdint>

// ============================================================================
// Fused flash attention via mma.sync (HMMA, base sm_103 target):
//   O = dropout(softmax(Q K^T * sqrt(128))) V,  B=4, SEQ=4096, H=128, fp32.
// QK and PV as bf16 m16n8k16 MMAs with 3-way fp32-emulation splits.
// Dropout = JAX partitionable threefry2x32, key (0,42), bits = o1^o2,
// keep <=> bits < 7549747*512  (bit-exact, verified round 2).
// Round 8: WARP SPECIALIZATION. 384 threads = 8 consumer warps (MMA/softmax)
// + 4 producer warps (threefry masks for iter i+1 -> double-buffered smem).
// 3 warps/SMSP so producer ALU ops fill consumer stall slots.
// ============================================================================

namespace cfg {
constexpr int H = 128, SEQ = 4096, BQ = 128, BK = 64;
constexpr int NIT = SEQ / BK;                      // 64
constexpr int THREADS = 384;                       // 8 consumer + 4 producer warps
constexpr uint32_t KEEP = 3865470464u;
// sqrt(128) * log2(e): logits computed directly in log2 units
constexpr float SCALE = 11.313708498984760390f * 1.4426950408889634074f;
constexpr int RS     = 272;                        // bf16 row stride bytes
constexpr int QTILE  = BQ * RS;                    // 34816
constexpr int KTILE  = BK * RS;                    // 17408
constexpr int SM_MASK = 0;                         // 2 x 256 uint32 = 2048 B
constexpr int SM_QHI  = 2048;
constexpr int SM_QLO  = SM_QHI + QTILE;
constexpr int SM_BUF0 = SM_QLO + QTILE;            // 71680
constexpr int BUFSZ   = 4 * KTILE;                 // KHI|KLO|VHI|VLO = 69632
constexpr int SMEM_TOTAL = SM_BUF0 + 2 * BUFSZ;    // 210944 B
}

// ---------------------------------------------------------------------------
// 8-way interleaved threefry-2x32-20, key (0,42), ctr (0,m) -> o1^o2
#define TFR8(r) \
    _Pragma("unroll") \
    for (int j = 0; j < 8; ++j) { \
        a[j] += b[j]; b[j] = __funnelshift_l(b[j], b[j], (r)); b[j] ^= a[j]; }
#define TFI8(ka, kb) \
    _Pragma("unroll") \
    for (int j = 0; j < 8; ++j) { a[j] += (ka); b[j] += (kb); }

__device__ __forceinline__ void tf8(const uint32_t* ctr, uint32_t* out) {
    const uint32_t K1 = 42u, K2 = 0x1BD11BF0u;
    uint32_t a[8], b[8];
    #pragma unroll
    for (int j = 0; j < 8; ++j) { a[j] = 0u; b[j] = ctr[j] + K1; }
    TFR8(13) TFR8(15) TFR8(26) TFR8(6)
    TFI8(K1, K2 + 1u)
    TFR8(17) TFR8(29) TFR8(16) TFR8(24)
    TFI8(K2, 2u)
    TFR8(13) TFR8(15) TFR8(26) TFR8(6)
    TFI8(0u, K1 + 3u)
    TFR8(17) TFR8(29) TFR8(16) TFR8(24)
    TFI8(K1, K2 + 4u)
    TFR8(13) TFR8(15) TFR8(26) TFR8(6)
    TFI8(K2, 5u)
    #pragma unroll
    for (int j = 0; j < 8; ++j) out[j] = a[j] ^ b[j];
}

// ---------------------------------------------------------------------------
__device__ __forceinline__ uint32_t smem_u32(const void* p) {
    uint32_t a;
    asm("{ .reg .u64 t; cvta.to.shared.u64 t, %1; cvt.u32.u64 %0, t; }" : "=r"(a) : "l"(p));
    return a;
}
__device__ __forceinline__ void ldsm4(uint32_t* r, uint32_t addr) {
    asm volatile("ldmatrix.sync.aligned.m8n8.x4.shared.b16 {%0,%1,%2,%3}, [%4];"
                 : "=r"(r[0]), "=r"(r[1]), "=r"(r[2]), "=r"(r[3]) : "r"(addr));
}
__device__ __forceinline__ void ldsm4t(uint32_t* r, uint32_t addr) {
    asm volatile("ldmatrix.sync.aligned.m8n8.x4.trans.shared.b16 {%0,%1,%2,%3}, [%4];"
                 : "=r"(r[0]), "=r"(r[1]), "=r"(r[2]), "=r"(r[3]) : "r"(addr));
}
__device__ __forceinline__ void mma16816(float* d, const uint32_t* a, uint32_t b0, uint32_t b1) {
    asm volatile("mma.sync.aligned.m16n8k16.row.col.f32.bf16.bf16.f32 "
                 "{%0,%1,%2,%3}, {%4,%5,%6,%7}, {%8,%9}, {%0,%1,%2,%3};"
                 : "+f"(d[0]), "+f"(d[1]), "+f"(d[2]), "+f"(d[3])
                 : "r"(a[0]), "r"(a[1]), "r"(a[2]), "r"(a[3]), "r"(b0), "r"(b1));
}
__device__ __forceinline__ float ex2f(float x) {
    float r; asm("ex2.approx.f32 %0, %1;" : "=f"(r) : "f"(x)); return r;
}
// split (x,y) -> hi bf16x2 pack, lo bf16x2 pack (bitwise = __float2bfloat16 seq)
__device__ __forceinline__ void split2f(float x, float y, uint32_t& hi, uint32_t& lo) {
    uint32_t h;
    asm("cvt.rn.bf16x2.f32 %0, %1, %2;" : "=r"(h) : "f"(y), "f"(x));
    float fx = __uint_as_float(h << 16);
    float fy = __uint_as_float(h & 0xffff0000u);
    uint32_t l;
    asm("cvt.rn.bf16x2.f32 %0, %1, %2;" : "=r"(l) : "f"(y - fy), "f"(x - fx));
    hi = h; lo = l;
}

// producer: compute packed keep-words for 2 consumer lanes at kv block vbn
__device__ __forceinline__ void produce_mask(uint32_t* maskw, int pt, int qblk,
                                             int bb, int vbn) {
    using namespace cfg;
    #pragma unroll
    for (int e = 0; e < 2; ++e) {
        int cl = pt * 2 + e;
        int w = cl >> 5, l = cl & 31;
        uint32_t mrow0 = ((uint32_t)bb << 24) | ((uint32_t)(qblk + w * 16 + (l >> 2)) << 12);
        uint32_t mrow1 = mrow0 + (8u << 12);
        uint32_t keep = 0u;
        #pragma unroll
        for (int ks = 0; ks < 4; ++ks) {
            uint32_t ctr[8], bits[8];
            #pragma unroll
            for (int h2 = 0; h2 < 2; ++h2) {
                uint32_t c = (uint32_t)(vbn + (2 * ks + h2) * 8 + (l & 3) * 2);
                ctr[h2 * 4 + 0] = mrow0 + c;
                ctr[h2 * 4 + 1] = mrow0 + c + 1u;
                ctr[h2 * 4 + 2] = mrow1 + c;
                ctr[h2 * 4 + 3] = mrow1 + c + 1u;
            }
            tf8(ctr, bits);
            #pragma unroll
            for (int t = 0; t < 8; ++t)
                if (bits[t] < KEEP) keep |= 1u << (ks * 8 + t);
        }
        maskw[cl] = keep;
    }
}

// ---------------------------------------------------------------------------
__global__ __launch_bounds__(cfg::THREADS, 1)
void attn_hmma_kernel(const float* __restrict__ Qg_,
                      const float* __restrict__ Kg_,
                      const float* __restrict__ Vg_,
                      float* __restrict__ Og) {
    using namespace cfg;
    extern __shared__ char smem[];
    const uint32_t sb = smem_u32(smem);
    uint32_t* maskS = (uint32_t*)(smem + SM_MASK);

    const int tid  = threadIdx.x;
    const int wid  = tid >> 5;
    const int lane = tid & 31;
    const bool consumer = (wid < 8);
    const int qblk = blockIdx.x * BQ;
    const int bb   = blockIdx.y;

    const float* Qg = Qg_ + (size_t)bb * SEQ * H;
    const float* Kg = Kg_ + (size_t)bb * SEQ * H;
    const float* Vg = Vg_ + (size_t)bb * SEQ * H;

    // ---- prologue ----
    if (consumer) {
        // load Q tile (scaled by sqrt(128)*log2e), split hi/lo
        #pragma unroll
        for (int i = 0; i < 16; ++i) {
            int idx = tid + i * 256;
            int row = idx >> 5, c4 = (idx & 31) << 2;
            float4 v = *(const float4*)(Qg + (size_t)(qblk + row) * H + c4);
            v.x *= SCALE; v.y *= SCALE; v.z *= SCALE; v.w *= SCALE;
            uint32_t h0, l0, h1, l1;
            split2f(v.x, v.y, h0, l0); split2f(v.z, v.w, h1, l1);
            *(uint2*)(smem + SM_QHI + row * RS + c4 * 2) = make_uint2(h0, h1);
            *(uint2*)(smem + SM_QLO + row * RS + c4 * 2) = make_uint2(l0, l1);
        }
        // prefetch K/V tile 0 into buffer 0
        #pragma unroll
        for (int i = 0; i < 8; ++i) {
            int idx = tid + i * 256;
            int row = idx >> 5, c4 = (idx & 31) << 2;
            float4 v = *(const float4*)(Kg + (size_t)row * H + c4);
            uint32_t h0, l0, h1, l1;
            split2f(v.x, v.y, h0, l0); split2f(v.z, v.w, h1, l1);
            *(uint2*)(smem + SM_BUF0 + row * RS + c4 * 2) = make_uint2(h0, h1);
            *(uint2*)(smem + SM_BUF0 + KTILE + row * RS + c4 * 2) = make_uint2(l0, l1);
        }
        #pragma unroll
        for (int i = 0; i < 8; ++i) {
            int idx = tid + i * 256;
            int row = idx >> 5, c4 = (idx & 31) << 2;
            float4 v = *(const float4*)(Vg + (size_t)row * H + c4);
            uint32_t h0, l0, h1, l1;
            split2f(v.x, v.y, h0, l0); split2f(v.z, v.w, h1, l1);
            *(uint2*)(smem + SM_BUF0 + 2 * KTILE + row * RS + c4 * 2) = make_uint2(h0, h1);
            *(uint2*)(smem + SM_BUF0 + 3 * KTILE + row * RS + c4 * 2) = make_uint2(l0, l1);
        }
    } else {
        produce_mask(maskS, tid - 256, qblk, bb, 0);   // mask for iter 0
    }

    const uint32_t abase   = sb + SM_QHI + (wid * 16 + (lane & 15)) * RS + (lane >> 4) * 16;
    const uint32_t kb_lane = (lane & 15) * RS + (lane >> 4) * 16;

    float o[16][4];
    #pragma unroll
    for (int j = 0; j < 16; ++j)
        #pragma unroll
        for (int c = 0; c < 4; ++c) o[j][c] = 0.0f;
    float m0 = -1e30f, m1 = -1e30f, l0 = 0.0f, l1 = 0.0f;

    for (int it = 0; it < NIT; ++it) {
        const int vb = it * BK;
        __syncthreads();   // mask[it&1] + KV buf[it&1] ready; prior reads done

        if (consumer) {
            // ---- prefetch K/V tile it+1 into the other buffer ----
            if (it + 1 < NIT) {
                const int vb2 = vb + BK;
                char* bufn = smem + SM_BUF0 + ((it + 1) & 1) * BUFSZ;
                #pragma unroll
                for (int i = 0; i < 8; ++i) {
                    int idx = tid + i * 256;
                    int row = idx >> 5, c4 = (idx & 31) << 2;
                    float4 v = *(const float4*)(Kg + (size_t)(vb2 + row) * H + c4);
                    uint32_t h0, l0_, h1, l1_;
                    split2f(v.x, v.y, h0, l0_); split2f(v.z, v.w, h1, l1_);
                    *(uint2*)(bufn + row * RS + c4 * 2) = make_uint2(h0, h1);
                    *(uint2*)(bufn + KTILE + row * RS + c4 * 2) = make_uint2(l0_, l1_);
                }
                #pragma unroll
                for (int i = 0; i < 8; ++i) {
                    int idx = tid + i * 256;
                    int row = idx >> 5, c4 = (idx & 31) << 2;
                    float4 v = *(const float4*)(Vg + (size_t)(vb2 + row) * H + c4);
                    uint32_t h0, l0_, h1, l1_;
                    split2f(v.x, v.y, h0, l0_); split2f(v.z, v.w, h1, l1_);
                    *(uint2*)(bufn + 2 * KTILE + row * RS + c4 * 2) = make_uint2(h0, h1);
                    *(uint2*)(bufn + 3 * KTILE + row * RS + c4 * 2) = make_uint2(l0_, l1_);
                }
            }

            const uint32_t bufc = sb + SM_BUF0 + (uint32_t)((it & 1) * BUFSZ);
            const uint32_t bK = bufc + kb_lane;
            const uint32_t bV = bufc + 2 * KTILE + kb_lane;

            // ---- S = Qh*Kh + Qh*Kl + Ql*Kh ----
            float s[8][4];
            #pragma unroll
            for (int j = 0; j < 8; ++j)
                #pragma unroll
                for (int c = 0; c < 4; ++c) s[j][c] = 0.0f;

            #pragma unroll
            for (int ks = 0; ks < 8; ++ks) {
                uint32_t ah[4], al[4];
                ldsm4(ah, abase + ks * 32);
                ldsm4(al, abase + QTILE + ks * 32);
                #pragma unroll
                for (int np = 0; np < 2; ++np) {
                    uint32_t bh0[4], bl0[4], bh1[4], bl1[4];
                    ldsm4(bh0, bK + (2 * np) * (16 * RS) + ks * 32);
                    ldsm4(bl0, bK + KTILE + (2 * np) * (16 * RS) + ks * 32);
                    ldsm4(bh1, bK + (2 * np + 1) * (16 * RS) + ks * 32);
                    ldsm4(bl1, bK + KTILE + (2 * np + 1) * (16 * RS) + ks * 32);
                    float* s0 = s[4 * np];     float* s1 = s[4 * np + 1];
                    float* s2 = s[4 * np + 2]; float* s3 = s[4 * np + 3];
                    mma16816(s0, ah, bh0[0], bh0[2]);
                    mma16816(s1, ah, bh0[1], bh0[3]);
                    mma16816(s2, ah, bh1[0], bh1[2]);
                    mma16816(s3, ah, bh1[1], bh1[3]);
                    mma16816(s0, ah, bl0[0], bl0[2]);
                    mma16816(s1, ah, bl0[1], bl0[3]);
                    mma16816(s2, ah, bl1[0], bl1[2]);
                    mma16816(s3, ah, bl1[1], bl1[3]);
                    mma16816(s0, al, bh0[0], bh0[2]);
                    mma16816(s1, al, bh0[1], bh0[3]);
                    mma16816(s2, al, bh1[0], bh1[2]);
                    mma16816(s3, al, bh1[1], bh1[3]);
                }
            }

            // ---- online softmax (log2 units) ----
            float mx0 = -1e30f, mx1 = -1e30f;
            #pragma unroll
            for (int j = 0; j < 8; ++j) {
                mx0 = fmaxf(mx0, fmaxf(s[j][0], s[j][1]));
                mx1 = fmaxf(mx1, fmaxf(s[j][2], s[j][3]));
            }
            #pragma unroll
            for (int off = 1; off < 4; off <<= 1) {
                mx0 = fmaxf(mx0, __shfl_xor_sync(0xffffffffu, mx0, off));
                mx1 = fmaxf(mx1, __shfl_xor_sync(0xffffffffu, mx1, off));
            }
            float mn0 = fmaxf(m0, mx0), mn1 = fmaxf(m1, mx1);
            float al0 = ex2f(m0 - mn0), al1 = ex2f(m1 - mn1);
            m0 = mn0; m1 = mn1;

            float ls0 = 0.0f, ls1 = 0.0f;
            #pragma unroll
            for (int j = 0; j < 8; ++j) {
                s[j][0] = ex2f(s[j][0] - mn0); ls0 += s[j][0];
                s[j][1] = ex2f(s[j][1] - mn0); ls0 += s[j][1];
                s[j][2] = ex2f(s[j][2] - mn1); ls1 += s[j][2];
                s[j][3] = ex2f(s[j][3] - mn1); ls1 += s[j][3];
            }
            #pragma unroll
            for (int off = 1; off < 4; off <<= 1) {
                ls0 += __shfl_xor_sync(0xffffffffu, ls0, off);
                ls1 += __shfl_xor_sync(0xffffffffu, ls1, off);
            }
            l0 = l0 * al0 + ls0;
            l1 = l1 * al1 + ls1;

            #pragma unroll
            for (int j = 0; j < 16; ++j) {
                o[j][0] *= al0; o[j][1] *= al0;
                o[j][2] *= al1; o[j][3] *= al1;
            }

            // ---- read precomputed keep-word, build P per-ks, PV MMAs ----
            const uint32_t keep = maskS[(it & 1) * 256 + wid * 32 + lane];
            #pragma unroll
            for (int ks = 0; ks < 4; ++ks) {
                uint32_t phi4[4], plo4[4];
                #pragma unroll
                for (int h2 = 0; h2 < 2; ++h2) {
                    int j = 2 * ks + h2;
                    uint32_t kb = keep >> (ks * 8 + h2 * 4);
                    float p0 = (kb & 1u) ? s[j][0] : 0.0f;
                    float p1 = (kb & 2u) ? s[j][1] : 0.0f;
                    float p2 = (kb & 4u) ? s[j][2] : 0.0f;
                    float p3 = (kb & 8u) ? s[j][3] : 0.0f;
                    split2f(p0, p1, phi4[h2 * 2],     plo4[h2 * 2]);
                    split2f(p2, p3, phi4[h2 * 2 + 1], plo4[h2 * 2 + 1]);
                }
                #pragma unroll
                for (int hp = 0; hp < 4; ++hp) {
                    uint32_t bh0[4], bl0[4], bh1[4], bl1[4];
                    ldsm4t(bh0, bV + ks * (16 * RS) + (2 * hp) * 32);
                    ldsm4t(bl0, bV + KTILE + ks * (16 * RS) + (2 * hp) * 32);
                    ldsm4t(bh1, bV + ks * (16 * RS) + (2 * hp + 1) * 32);
                    ldsm4t(bl1, bV + KTILE + ks * (16 * RS) + (2 * hp + 1) * 32);
                    float* o0 = o[4 * hp];     float* o1 = o[4 * hp + 1];
                    float* o2 = o[4 * hp + 2]; float* o3 = o[4 * hp + 3];
                    mma16816(o0, phi4, bh0[0], bh0[1]);
                    mma16816(o1, phi4, bh0[2], bh0[3]);
                    mma16816(o2, phi4, bh1[0], bh1[1]);
                    mma16816(o3, phi4, bh1[2], bh1[3]);
                    mma16816(o0, phi4, bl0[0], bl0[1]);
                    mma16816(o1, phi4, bl0[2], bl0[3]);
                    mma16816(o2, phi4, bl1[0], bl1[1]);
                    mma16816(o3, phi4, bl1[2], bl1[3]);
                    mma16816(o0, plo4, bh0[0], bh0[1]);
                    mma16816(o1, plo4, bh0[2], bh0[3]);
                    mma16816(o2, plo4, bh1[0], bh1[1]);
                    mma16816(o3, plo4, bh1[2], bh1[3]);
                }
            }
        } else {
            // ---- producer: mask for iter it+1 into the other buffer ----
            if (it + 1 < NIT) {
                produce_mask(maskS + ((it + 1) & 1) * 256, tid - 256,
                             qblk, bb, (it + 1) * BK);
            }
        }
    }

    // ---- epilogue: consumers write O /= (0.9 * l) ----
    if (consumer) {
        const int row_g0 = qblk + wid * 16 + (lane >> 2);
        float inv0 = 1.0f / (0.9f * l0);
        float inv1 = 1.0f / (0.9f * l1);
        float* out0 = Og + ((size_t)bb * SEQ + row_g0) * H;
        float* out1 = out0 + 8 * H;
        #pragma unroll
        for (int j = 0; j < 16; ++j) {
            int h = j * 8 + (lane & 3) * 2;
            *(float2*)(out0 + h) = make_float2(o[j][0] * inv0, o[j][1] * inv0);
            *(float2*)(out1 + h) = make_float2(o[j][2] * inv1, o[j][3] * inv1);
        }
    }
}

extern "C" void kernel_launch(void* const* d_in, const int* in_sizes, int n_in,
                              void* d_out, int out_size) {
    const float* Q = (const float*)d_in[0];
    const float* K = (const float*)d_in[1];
    const float* V = (const float*)d_in[2];
    float* O = (float*)d_out;
    (void)in_sizes; (void)n_in; (void)out_size;

    cudaFuncSetAttribute(attn_hmma_kernel,
                         cudaFuncAttributeMaxDynamicSharedMemorySize, cfg::SMEM_TOTAL);
    dim3 grid(cfg::SEQ / cfg::BQ, 4);
    attn_hmma_kernel<<<grid, cfg::THREADS, cfg::SMEM_TOTAL>>>(Q, K, V, O);
}

// round 10
// speedup vs baseline: 1.6273x; 1.6273x over previous
#include <cuda_runtime.h>
#include <cuda_bf16.h>
#include <cstdint>

// ============================================================================
// Fused flash attention, 3-kernel decomposition (base sm_103 target):
//   O = dropout(softmax(Q K^T * sqrt(128))) V,  B=4, SEQ=4096, H=128, fp32.
// K1 split:  Q(scaled)/K/V -> bf16 hi/lo device globals (split once, not 32x).
// K2 mask:   all threefry keep-words (bit-exact JAX partitionable threefry,
//            key (0,42), bits=o1^o2, keep <=> bits < 7549747*512) -> 8MB global.
// K3 attn:   round-6 HMMA flash kernel, threefry/split removed, K/V tiles via
//            cp.async.cg from the pre-split arrays, mask via 1 LDG/lane/iter.
// ============================================================================

namespace cfg {
constexpr int H = 128, SEQ = 4096, BQ = 128, BK = 64;
constexpr int NIT = SEQ / BK;                      // 64
constexpr int THREADS = 256;
constexpr uint32_t KEEP = 3865470464u;
// sqrt(128) * log2(e): logits carried in log2 units (ex2 softmax)
constexpr float SCALE = 11.313708498984760390f * 1.4426950408889634074f;
constexpr int RS     = 272;                        // bf16 row stride bytes
constexpr int QTILE  = BQ * RS;                    // 34816
constexpr int KTILE  = BK * RS;                    // 17408
constexpr int SM_QHI = 0;
constexpr int SM_QLO = QTILE;
constexpr int SM_BUF0 = 2 * QTILE;                 // 69632
constexpr int BUFSZ  = 4 * KTILE;                  // KHI|KLO|VHI|VLO
constexpr int SMEM_TOTAL = SM_BUF0 + 2 * BUFSZ;    // 208896 B
constexpr int NELEM4 = 4 * SEQ * H / 4;            // 524288 float4 per tensor
}

// ---- device globals: pre-split operands + packed dropout mask --------------
__device__ __align__(16) uint32_t g_Qhi[1048576];   // 4 MB each (bf16 pairs)
__device__ __align__(16) uint32_t g_Qlo[1048576];
__device__ __align__(16) uint32_t g_Khi[1048576];
__device__ __align__(16) uint32_t g_Klo[1048576];
__device__ __align__(16) uint32_t g_Vhi[1048576];
__device__ __align__(16) uint32_t g_Vlo[1048576];
__device__ __align__(16) uint32_t g_mask[2097152];  // 8 MB keep-words

// ---------------------------------------------------------------------------
// 8-way interleaved threefry-2x32-20, key (0,42), ctr (0,m) -> o1^o2
#define TFR8(r) \
    _Pragma("unroll") \
    for (int j = 0; j < 8; ++j) { \
        a[j] += b[j]; b[j] = __funnelshift_l(b[j], b[j], (r)); b[j] ^= a[j]; }
#define TFI8(ka, kb) \
    _Pragma("unroll") \
    for (int j = 0; j < 8; ++j) { a[j] += (ka); b[j] += (kb); }

__device__ __forceinline__ void tf8(const uint32_t* ctr, uint32_t* out) {
    const uint32_t K1 = 42u, K2 = 0x1BD11BF0u;
    uint32_t a[8], b[8];
    #pragma unroll
    for (int j = 0; j < 8; ++j) { a[j] = 0u; b[j] = ctr[j] + K1; }
    TFR8(13) TFR8(15) TFR8(26) TFR8(6)
    TFI8(K1, K2 + 1u)
    TFR8(17) TFR8(29) TFR8(16) TFR8(24)
    TFI8(K2, 2u)
    TFR8(13) TFR8(15) TFR8(26) TFR8(6)
    TFI8(0u, K1 + 3u)
    TFR8(17) TFR8(29) TFR8(16) TFR8(24)
    TFI8(K1, K2 + 4u)
    TFR8(13) TFR8(15) TFR8(26) TFR8(6)
    TFI8(K2, 5u)
    #pragma unroll
    for (int j = 0; j < 8; ++j) out[j] = a[j] ^ b[j];
}

// ---------------------------------------------------------------------------
__device__ __forceinline__ uint32_t smem_u32(const void* p) {
    uint32_t a;
    asm("{ .reg .u64 t; cvta.to.shared.u64 t, %1; cvt.u32.u64 %0, t; }" : "=r"(a) : "l"(p));
    return a;
}
__device__ __forceinline__ void cpa16(uint32_t dst, const void* src) {
    asm volatile("cp.async.cg.shared.global [%0], [%1], 16;" :: "r"(dst), "l"(src) : "memory");
}
__device__ __forceinline__ void cpa_commit() {
    asm volatile("cp.async.commit_group;" ::: "memory");
}
__device__ __forceinline__ void cpa_wait0() {
    asm volatile("cp.async.wait_group 0;" ::: "memory");
}
__device__ __forceinline__ void ldsm4(uint32_t* r, uint32_t addr) {
    asm volatile("ldmatrix.sync.aligned.m8n8.x4.shared.b16 {%0,%1,%2,%3}, [%4];"
                 : "=r"(r[0]), "=r"(r[1]), "=r"(r[2]), "=r"(r[3]) : "r"(addr));
}
__device__ __forceinline__ void ldsm4t(uint32_t* r, uint32_t addr) {
    asm volatile("ldmatrix.sync.aligned.m8n8.x4.trans.shared.b16 {%0,%1,%2,%3}, [%4];"
                 : "=r"(r[0]), "=r"(r[1]), "=r"(r[2]), "=r"(r[3]) : "r"(addr));
}
__device__ __forceinline__ void mma16816(float* d, const uint32_t* a, uint32_t b0, uint32_t b1) {
    asm volatile("mma.sync.aligned.m16n8k16.row.col.f32.bf16.bf16.f32 "
                 "{%0,%1,%2,%3}, {%4,%5,%6,%7}, {%8,%9}, {%0,%1,%2,%3};"
                 : "+f"(d[0]), "+f"(d[1]), "+f"(d[2]), "+f"(d[3])
                 : "r"(a[0]), "r"(a[1]), "r"(a[2]), "r"(a[3]), "r"(b0), "r"(b1));
}
__device__ __forceinline__ float ex2f(float x) {
    float r; asm("ex2.approx.f32 %0, %1;" : "=f"(r) : "f"(x)); return r;
}
// split (x,y) -> hi bf16x2 pack, lo bf16x2 pack (bitwise = __float2bfloat16 seq)
__device__ __forceinline__ void split2f(float x, float y, uint32_t& hi, uint32_t& lo) {
    uint32_t h;
    asm("cvt.rn.bf16x2.f32 %0, %1, %2;" : "=r"(h) : "f"(y), "f"(x));
    float fx = __uint_as_float(h << 16);
    float fy = __uint_as_float(h & 0xffff0000u);
    uint32_t l;
    asm("cvt.rn.bf16x2.f32 %0, %1, %2;" : "=r"(l) : "f"(y - fy), "f"(x - fx));
    hi = h; lo = l;
}

// ============================================================================
// Kernel 1: split Q/K/V into bf16 hi/lo (Q pre-scaled)
// ============================================================================
__global__ __launch_bounds__(256)
void split_kernel(const float* __restrict__ Q,
                  const float* __restrict__ K,
                  const float* __restrict__ V) {
    using namespace cfg;
    const int i0 = blockIdx.x * 256 + threadIdx.x;
    #pragma unroll
    for (int r = 0; r < 2; ++r) {
        int i = i0 + r * 262144;            // < 524288
        float4 v = ((const float4*)Q)[i];
        v.x *= SCALE; v.y *= SCALE; v.z *= SCALE; v.w *= SCALE;
        uint32_t h0, l0, h1, l1;
        split2f(v.x, v.y, h0, l0); split2f(v.z, v.w, h1, l1);
        ((uint2*)g_Qhi)[i] = make_uint2(h0, h1);
        ((uint2*)g_Qlo)[i] = make_uint2(l0, l1);

        v = ((const float4*)K)[i];
        split2f(v.x, v.y, h0, l0); split2f(v.z, v.w, h1, l1);
        ((uint2*)g_Khi)[i] = make_uint2(h0, h1);
        ((uint2*)g_Klo)[i] = make_uint2(l0, l1);

        v = ((const float4*)V)[i];
        split2f(v.x, v.y, h0, l0); split2f(v.z, v.w, h1, l1);
        ((uint2*)g_Vhi)[i] = make_uint2(h0, h1);
        ((uint2*)g_Vlo)[i] = make_uint2(l0, l1);
    }
}

// ============================================================================
// Kernel 2: all dropout keep-words (bit-exact threefry), one word per thread
//   word t: lane=t&31, wid=(t>>5)&7, it=(t>>8)&63, qt=(t>>14)&31, b=t>>19
// ============================================================================
__global__ __launch_bounds__(256)
void mask_kernel() {
    using namespace cfg;
    const uint32_t t = blockIdx.x * 256 + threadIdx.x;
    const int lane = t & 31;
    const int wid  = (t >> 5) & 7;
    const int it   = (t >> 8) & 63;
    const int qt   = (t >> 14) & 31;
    const int bb   = t >> 19;

    const int qrow = qt * BQ + wid * 16 + (lane >> 2);
    const uint32_t mrow0 = ((uint32_t)bb << 24) | ((uint32_t)qrow << 12);
    const uint32_t mrow1 = mrow0 + (8u << 12);
    const int vb = it * BK;

    uint32_t keep = 0u;
    #pragma unroll
    for (int ks = 0; ks < 4; ++ks) {
        uint32_t ctr[8], bits[8];
        #pragma unroll
        for (int h2 = 0; h2 < 2; ++h2) {
            uint32_t c = (uint32_t)(vb + (2 * ks + h2) * 8 + (lane & 3) * 2);
            ctr[h2 * 4 + 0] = mrow0 + c;
            ctr[h2 * 4 + 1] = mrow0 + c + 1u;
            ctr[h2 * 4 + 2] = mrow1 + c;
            ctr[h2 * 4 + 3] = mrow1 + c + 1u;
        }
        tf8(ctr, bits);
        #pragma unroll
        for (int u = 0; u < 8; ++u)
            if (bits[u] < KEEP) keep |= 1u << (ks * 8 + u);
    }
    g_mask[t] = keep;
}

// ============================================================================
// Kernel 3: flash attention (HMMA), pre-split operands via cp.async
// ============================================================================
__global__ __launch_bounds__(cfg::THREADS, 1)
void attn_hmma_kernel(float* __restrict__ Og) {
    using namespace cfg;
    extern __shared__ char smem[];
    const uint32_t sb = smem_u32(smem);

    const int tid  = threadIdx.x;
    const int wid  = tid >> 5;
    const int lane = tid & 31;
    const int qt   = blockIdx.x;
    const int qblk = qt * BQ;
    const int bb   = blockIdx.y;

    const size_t tbase = (size_t)bb * SEQ * H;     // element offset of batch

    // ---- prologue: cp.async Q tile (hi+lo) and K/V tile 0 ----
    {
        const char* qh = (const char*)g_Qhi + (tbase + (size_t)qblk * H) * 2;
        const char* ql = (const char*)g_Qlo + (tbase + (size_t)qblk * H) * 2;
        #pragma unroll
        for (int i = 0; i < 8; ++i) {               // 2048 16B chunks / 256 thr
            int idx = tid + i * 256;
            int row = idx >> 4, c = idx & 15;
            cpa16(sb + SM_QHI + row * RS + c * 16, qh + row * 256 + c * 16);
            cpa16(sb + SM_QLO + row * RS + c * 16, ql + row * 256 + c * 16);
        }
        const char* kh = (const char*)g_Khi + tbase * 2;
        const char* kl = (const char*)g_Klo + tbase * 2;
        const char* vh = (const char*)g_Vhi + tbase * 2;
        const char* vl = (const char*)g_Vlo + tbase * 2;
        #pragma unroll
        for (int j = 0; j < 4; ++j) {               // 1024 chunks per array
            int idx = tid + j * 256;
            int row = idx >> 4, c = idx & 15;
            uint32_t d = sb + SM_BUF0 + row * RS + c * 16;
            int      s = row * 256 + c * 16;
            cpa16(d,             kh + s);
            cpa16(d + KTILE,     kl + s);
            cpa16(d + 2 * KTILE, vh + s);
            cpa16(d + 3 * KTILE, vl + s);
        }
        cpa_commit();
        cpa_wait0();
    }
    __syncthreads();

    const uint32_t abase   = sb + SM_QHI + (wid * 16 + (lane & 15)) * RS + (lane >> 4) * 16;
    const uint32_t kb_lane = (lane & 15) * RS + (lane >> 4) * 16;
    const uint32_t mbase   = ((uint32_t)bb * 32 + (uint32_t)qt) * 64u;

    float o[16][4];
    #pragma unroll
    for (int j = 0; j < 16; ++j)
        #pragma unroll
        for (int c = 0; c < 4; ++c) o[j][c] = 0.0f;
    float m0 = -1e30f, m1 = -1e30f, l0 = 0.0f, l1 = 0.0f;

    for (int it = 0; it < NIT; ++it) {
        // ---- fetch this iter's keep word early (L2-resident) ----
        const uint32_t keep = g_mask[(mbase + (uint32_t)it) * 256u + wid * 32 + lane];

        // ---- cp.async K/V tile it+1 into the other buffer ----
        if (it + 1 < NIT) {
            const size_t vb2 = (size_t)(it + 1) * BK;
            uint32_t bufn = sb + SM_BUF0 + (uint32_t)(((it + 1) & 1) * BUFSZ);
            const char* kh = (const char*)g_Khi + (tbase + vb2 * H) * 2;
            const char* kl = (const char*)g_Klo + (tbase + vb2 * H) * 2;
            const char* vh = (const char*)g_Vhi + (tbase + vb2 * H) * 2;
            const char* vl = (const char*)g_Vlo + (tbase + vb2 * H) * 2;
            #pragma unroll
            for (int j = 0; j < 4; ++j) {
                int idx = tid + j * 256;
                int row = idx >> 4, c = idx & 15;
                uint32_t d = bufn + row * RS + c * 16;
                int      s = row * 256 + c * 16;
                cpa16(d,             kh + s);
                cpa16(d + KTILE,     kl + s);
                cpa16(d + 2 * KTILE, vh + s);
                cpa16(d + 3 * KTILE, vl + s);
            }
            cpa_commit();
        }

        const uint32_t bufc = sb + SM_BUF0 + (uint32_t)((it & 1) * BUFSZ);
        const uint32_t bK = bufc + kb_lane;
        const uint32_t bV = bufc + 2 * KTILE + kb_lane;

        // ---- S = Qh*Kh + Qh*Kl + Ql*Kh  (16 x 64 per warp, dep distance 4) ----
        float s[8][4];
        #pragma unroll
        for (int j = 0; j < 8; ++j)
            #pragma unroll
            for (int c = 0; c < 4; ++c) s[j][c] = 0.0f;

        #pragma unroll
        for (int ks = 0; ks < 8; ++ks) {
            uint32_t ah[4], al[4];
            ldsm4(ah, abase + ks * 32);
            ldsm4(al, abase + QTILE + ks * 32);
            #pragma unroll
            for (int np = 0; np < 2; ++np) {
                uint32_t bh0[4], bl0[4], bh1[4], bl1[4];
                ldsm4(bh0, bK + (2 * np) * (16 * RS) + ks * 32);
                ldsm4(bl0, bK + KTILE + (2 * np) * (16 * RS) + ks * 32);
                ldsm4(bh1, bK + (2 * np + 1) * (16 * RS) + ks * 32);
                ldsm4(bl1, bK + KTILE + (2 * np + 1) * (16 * RS) + ks * 32);
                float* s0 = s[4 * np];     float* s1 = s[4 * np + 1];
                float* s2 = s[4 * np + 2]; float* s3 = s[4 * np + 3];
                mma16816(s0, ah, bh0[0], bh0[2]);
                mma16816(s1, ah, bh0[1], bh0[3]);
                mma16816(s2, ah, bh1[0], bh1[2]);
                mma16816(s3, ah, bh1[1], bh1[3]);
                mma16816(s0, ah, bl0[0], bl0[2]);
                mma16816(s1, ah, bl0[1], bl0[3]);
                mma16816(s2, ah, bl1[0], bl1[2]);
                mma16816(s3, ah, bl1[1], bl1[3]);
                mma16816(s0, al, bh0[0], bh0[2]);
                mma16816(s1, al, bh0[1], bh0[3]);
                mma16816(s2, al, bh1[0], bh1[2]);
                mma16816(s3, al, bh1[1], bh1[3]);
            }
        }

        // ---- online softmax (log2 units) ----
        float mx0 = -1e30f, mx1 = -1e30f;
        #pragma unroll
        for (int j = 0; j < 8; ++j) {
            mx0 = fmaxf(mx0, fmaxf(s[j][0], s[j][1]));
            mx1 = fmaxf(mx1, fmaxf(s[j][2], s[j][3]));
        }
        #pragma unroll
        for (int off = 1; off < 4; off <<= 1) {
            mx0 = fmaxf(mx0, __shfl_xor_sync(0xffffffffu, mx0, off));
            mx1 = fmaxf(mx1, __shfl_xor_sync(0xffffffffu, mx1, off));
        }
        float mn0 = fmaxf(m0, mx0), mn1 = fmaxf(m1, mx1);
        float al0 = ex2f(m0 - mn0), al1 = ex2f(m1 - mn1);
        m0 = mn0; m1 = mn1;

        float ls0 = 0.0f, ls1 = 0.0f;
        #pragma unroll
        for (int j = 0; j < 8; ++j) {
            s[j][0] = ex2f(s[j][0] - mn0); ls0 += s[j][0];
            s[j][1] = ex2f(s[j][1] - mn0); ls0 += s[j][1];
            s[j][2] = ex2f(s[j][2] - mn1); ls1 += s[j][2];
            s[j][3] = ex2f(s[j][3] - mn1); ls1 += s[j][3];
        }
        #pragma unroll
        for (int off = 1; off < 4; off <<= 1) {
            ls0 += __shfl_xor_sync(0xffffffffu, ls0, off);
            ls1 += __shfl_xor_sync(0xffffffffu, ls1, off);
        }
        l0 = l0 * al0 + ls0;
        l1 = l1 * al1 + ls1;

        #pragma unroll
        for (int j = 0; j < 16; ++j) {
            o[j][0] *= al0; o[j][1] *= al0;
            o[j][2] *= al1; o[j][3] *= al1;
        }

        // ---- apply precomputed keep bits + build P hi/lo A-fragments ----
        uint32_t phi[4][4], plo[4][4];
        #pragma unroll
        for (int ks = 0; ks < 4; ++ks) {
            #pragma unroll
            for (int h2 = 0; h2 < 2; ++h2) {
                int j = 2 * ks + h2;
                uint32_t kb = keep >> (ks * 8 + h2 * 4);
                float p0 = (kb & 1u) ? s[j][0] : 0.0f;
                float p1 = (kb & 2u) ? s[j][1] : 0.0f;
                float p2 = (kb & 4u) ? s[j][2] : 0.0f;
                float p3 = (kb & 8u) ? s[j][3] : 0.0f;
                split2f(p0, p1, phi[ks][h2 * 2],     plo[ks][h2 * 2]);
                split2f(p2, p3, phi[ks][h2 * 2 + 1], plo[ks][h2 * 2 + 1]);
            }
        }

        // ---- O += Ph*Vh + Ph*Vl + Pl*Vh  (dep distance 4) ----
        #pragma unroll
        for (int ks = 0; ks < 4; ++ks) {
            #pragma unroll
            for (int hp = 0; hp < 4; ++hp) {
                uint32_t bh0[4], bl0[4], bh1[4], bl1[4];
                ldsm4t(bh0, bV + ks * (16 * RS) + (2 * hp) * 32);
                ldsm4t(bl0, bV + KTILE + ks * (16 * RS) + (2 * hp) * 32);
                ldsm4t(bh1, bV + ks * (16 * RS) + (2 * hp + 1) * 32);
                ldsm4t(bl1, bV + KTILE + ks * (16 * RS) + (2 * hp + 1) * 32);
                float* o0 = o[4 * hp];     float* o1 = o[4 * hp + 1];
                float* o2 = o[4 * hp + 2]; float* o3 = o[4 * hp + 3];
                mma16816(o0, phi[ks], bh0[0], bh0[1]);
                mma16816(o1, phi[ks], bh0[2], bh0[3]);
                mma16816(o2, phi[ks], bh1[0], bh1[1]);
                mma16816(o3, phi[ks], bh1[2], bh1[3]);
                mma16816(o0, phi[ks], bl0[0], bl0[1]);
                mma16816(o1, phi[ks], bl0[2], bl0[3]);
                mma16816(o2, phi[ks], bl1[0], bl1[1]);
                mma16816(o3, phi[ks], bl1[2], bl1[3]);
                mma16816(o0, plo[ks], bh0[0], bh0[1]);
                mma16816(o1, plo[ks], bh0[2], bh0[3]);
                mma16816(o2, plo[ks], bh1[0], bh1[1]);
                mma16816(o3, plo[ks], bh1[2], bh1[3]);
            }
        }

        // ---- ensure next tile arrived; barrier flips buffers ----
        cpa_wait0();
        __syncthreads();
    }

    // ---- epilogue: O /= (0.9 * l) ----
    const int row_g0 = qblk + wid * 16 + (lane >> 2);
    float inv0 = 1.0f / (0.9f * l0);
    float inv1 = 1.0f / (0.9f * l1);
    float* out0 = Og + ((size_t)bb * SEQ + row_g0) * H;
    float* out1 = out0 + 8 * H;
    #pragma unroll
    for (int j = 0; j < 16; ++j) {
        int h = j * 8 + (lane & 3) * 2;
        *(float2*)(out0 + h) = make_float2(o[j][0] * inv0, o[j][1] * inv0);
        *(float2*)(out1 + h) = make_float2(o[j][2] * inv1, o[j][3] * inv1);
    }
}

// ============================================================================
extern "C" void kernel_launch(void* const* d_in, const int* in_sizes, int n_in,
                              void* d_out, int out_size) {
    const float* Q = (const float*)d_in[0];
    const float* K = (const float*)d_in[1];
    const float* V = (const float*)d_in[2];
    float* O = (float*)d_out;
    (void)in_sizes; (void)n_in; (void)out_size;

    split_kernel<<<1024, 256>>>(Q, K, V);
    mask_kernel<<<8192, 256>>>();

    cudaFuncSetAttribute(attn_hmma_kernel,
                         cudaFuncAttributeMaxDynamicSharedMemorySize, cfg::SMEM_TOTAL);
    dim3 grid(cfg::SEQ / cfg::BQ, 4);
    attn_hmma_kernel<<<grid, cfg::THREADS, cfg::SMEM_TOTAL>>>(O);
}